// round 4
// baseline (speedup 1.0000x reference)
#include <cuda_runtime.h>
#include <math.h>

#define FRAME_SIZE 160
#define LPC_N 16
#define T_LEN 2400
#define T4 (T_LEN / 4)        // 600
#define N_FRAMES 15
#define B_SZ 1024

#define FPB 3                          // frames per block
#define CHUNK (FRAME_SIZE * FPB)       // 480 samples (per row)
#define CHUNKS_PER_B (N_FRAMES / FPB)  // 5
#define NTHREADS 128
#define NWORK (CHUNK / 4)              // 120 work items (4 t-steps x 2 rows each)

#define SCALE    (255.0f / 32768.0f)
#define SCALE_1  (32768.0f / 255.0f)

typedef unsigned long long u64;

__device__ __forceinline__ float ex2_approx(float x) {
    float y; asm("ex2.approx.f32 %0, %1;" : "=f"(y) : "f"(x)); return y;
}
__device__ __forceinline__ float lg2_approx(float x) {
    float y; asm("lg2.approx.f32 %0, %1;" : "=f"(y) : "f"(x)); return y;
}
// packed fp32x2 fused multiply-add (FFMA2) — PTX-only on sm_103a
__device__ __forceinline__ u64 ffma2(u64 a, u64 b, u64 c) {
    u64 d; asm("fma.rn.f32x2 %0, %1, %2, %3;" : "=l"(d) : "l"(a), "l"(b), "l"(c));
    return d;
}
__device__ __forceinline__ float lo32(u64 v) { return __uint_as_float((unsigned)v); }
__device__ __forceinline__ float hi32(u64 v) { return __uint_as_float((unsigned)(v >> 32)); }

// mu-law (0..255) -> linear.  exp(u/128*ln256) == 2^(u/16)
__device__ __forceinline__ float u2l(float v) {
    float u = v - 128.0f;
    float m = fmaf(SCALE_1, ex2_approx(fabsf(u) * 0.0625f), -SCALE_1);
    return copysignf(m, u);
}
// l2u(-x): clip(128 - copysign(16*log2(1 + SCALE*|x|), x), 0, 255)
__device__ __forceinline__ float l2u_neg(float x) {
    float u = 16.0f * lg2_approx(fmaf(SCALE, fabsf(x), 1.0f));
    return fminf(fmaxf(128.0f - copysignf(u, x), 0.0f), 255.0f);
}

__device__ __forceinline__ float4 dec4(float4 v) {
    float4 d;
    d.x = u2l(v.x); d.y = u2l(v.y); d.z = u2l(v.z); d.w = u2l(v.w);
    return d;
}

// One block = 2 batch rows x 480-sample chunk. Decoded samples stored as
// interleaved float2 pairs (lane0=row b0, lane1=row b0+1) in shared.
// FIR is processed in 4 tap-chunks of 4 taps each so the live register
// window stays small (8 window pairs + 4 coeff pairs + 4 accumulators).
__global__ __launch_bounds__(NTHREADS, 8)
void diff_pred_kernel(const float4* __restrict__ sig,
                      const float*  __restrict__ lpc,
                      float4* __restrict__ out) {
    __shared__ __align__(16) float2 sx2[LPC_N + CHUNK];  // halo + chunk, pairs
    __shared__ __align__(16) float2 sl2[FPB * LPC_N];    // coeff pairs

    const int bx  = blockIdx.x;
    const int p   = bx / CHUNKS_PER_B;     // row pair 0..511
    const int ck  = bx % CHUNKS_PER_B;     // chunk 0..4
    const int b0  = 2 * p;
    const int tid = threadIdx.x;
    const int base4 = ck * (CHUNK / 4);    // float4 offset of chunk in row

    if (tid < NWORK) {
        float4 d0 = dec4(sig[(size_t)b0 * T4 + base4 + tid]);
        float4 d1 = dec4(sig[(size_t)(b0 + 1) * T4 + base4 + tid]);
        float4* dst = (float4*)&sx2[LPC_N + 4 * tid];
        dst[0] = make_float4(d0.x, d1.x, d0.y, d1.y);
        dst[1] = make_float4(d0.z, d1.z, d0.w, d1.w);
    } else if (tid < NWORK + 4) {
        // halo: 16 samples preceding the chunk (zeros in linear domain at t<0)
        int k = tid - NWORK;               // 0..3
        float4* dst = (float4*)&sx2[4 * k];
        if (ck == 0) {
            dst[0] = make_float4(0.f, 0.f, 0.f, 0.f);
            dst[1] = make_float4(0.f, 0.f, 0.f, 0.f);
        } else {
            float4 d0 = dec4(sig[(size_t)b0 * T4 + base4 - 4 + k]);
            float4 d1 = dec4(sig[(size_t)(b0 + 1) * T4 + base4 - 4 + k]);
            dst[0] = make_float4(d0.x, d1.x, d0.y, d1.y);
            dst[1] = make_float4(d0.z, d1.z, d0.w, d1.w);
        }
    }
    if (tid < FPB * LPC_N) {
        int off = ck * (FPB * LPC_N) + tid;
        sl2[tid] = make_float2(lpc[(size_t)b0 * (N_FRAMES * LPC_N) + off],
                               lpc[(size_t)(b0 + 1) * (N_FRAMES * LPC_N) + off]);
    }
    __syncthreads();

    if (tid >= NWORK) return;

    const int f = tid / (FRAME_SIZE / 4);  // frame within chunk: 0..2
    const ulonglong2* cq2 = (const ulonglong2*)(sl2 + f * LPC_N);
    const ulonglong2* wq2 = (const ulonglong2*)(sx2 + 4 * tid);

    // acc_j = sum_i c[i] * w[16 + j - i]   (w = pair window sx2[4tid .. 4tid+19])
    // Tap-chunk k covers i = 4k..4k+3 and touches w pairs [12-4k .. 19-4k].
    u64 a0 = 0ull, a1 = 0ull, a2 = 0ull, a3 = 0ull;
#pragma unroll
    for (int k = 0; k < 4; ++k) {
        // 4 coefficient pairs for taps 4k..4k+3 (2 LDS.128)
        ulonglong2 cA = cq2[2 * k];
        ulonglong2 cB = cq2[2 * k + 1];
        // 8 window pairs w[12-4k .. 19-4k] (4 LDS.128); base pair idx 12-4k
        const int wb = (12 - 4 * k) / 2;   // ulonglong2 index
        ulonglong2 w0 = wq2[wb];
        ulonglong2 w1 = wq2[wb + 1];
        ulonglong2 w2 = wq2[wb + 2];
        ulonglong2 w3 = wq2[wb + 3];
        u64 W[8] = { w0.x, w0.y, w1.x, w1.y, w2.x, w2.y, w3.x, w3.y };
        // tap i = 4k+i2 uses local window index 4 + j - i2
        a0 = ffma2(cA.x, W[4], a0);  a1 = ffma2(cA.x, W[5], a1);
        a2 = ffma2(cA.x, W[6], a2);  a3 = ffma2(cA.x, W[7], a3);
        a0 = ffma2(cA.y, W[3], a0);  a1 = ffma2(cA.y, W[4], a1);
        a2 = ffma2(cA.y, W[5], a2);  a3 = ffma2(cA.y, W[6], a3);
        a0 = ffma2(cB.x, W[2], a0);  a1 = ffma2(cB.x, W[3], a1);
        a2 = ffma2(cB.x, W[4], a2);  a3 = ffma2(cB.x, W[5], a3);
        a0 = ffma2(cB.y, W[1], a0);  a1 = ffma2(cB.y, W[2], a1);
        a2 = ffma2(cB.y, W[3], a2);  a3 = ffma2(cB.y, W[4], a3);
    }

    float4 r0, r1;
    r0.x = l2u_neg(lo32(a0)); r1.x = l2u_neg(hi32(a0));
    r0.y = l2u_neg(lo32(a1)); r1.y = l2u_neg(hi32(a1));
    r0.z = l2u_neg(lo32(a2)); r1.z = l2u_neg(hi32(a2));
    r0.w = l2u_neg(lo32(a3)); r1.w = l2u_neg(hi32(a3));

    out[(size_t)b0 * T4 + base4 + tid] = r0;
    out[(size_t)(b0 + 1) * T4 + base4 + tid] = r1;
}

extern "C" void kernel_launch(void* const* d_in, const int* in_sizes, int n_in,
                              void* d_out, int out_size) {
    const float4* sig = (const float4*)d_in[0];  // (B, 2400, 1) f32
    const float*  lpc = (const float*)d_in[1];   // (B, 15, 16) f32
    float4* out = (float4*)d_out;                // (B, 2400, 1) f32

    dim3 grid((B_SZ / 2) * CHUNKS_PER_B);        // 2560 blocks
    dim3 block(NTHREADS);
    diff_pred_kernel<<<grid, block>>>(sig, lpc, out);
}

// round 5
// speedup vs baseline: 1.0029x; 1.0029x over previous
#include <cuda_runtime.h>
#include <math.h>

#define FRAME_SIZE 160
#define LPC_N 16
#define T_LEN 2400
#define T4 (T_LEN / 4)                 // 600 float4 per row
#define N_FRAMES 15
#define B_SZ 1024

#define FPB 3                          // frames per block
#define CHUNK (FRAME_SIZE * FPB)       // 480 samples
#define CHUNK4 (CHUNK / 4)             // 120 float4
#define CHUNKS_PER_B (N_FRAMES / FPB)  // 5
#define NTHREADS 64
#define NWORK (CHUNK / 8)              // 60 threads, 8 samples each

#define SCALE    (255.0f / 32768.0f)
#define SCALE_1  (32768.0f / 255.0f)

__device__ __forceinline__ float ex2_approx(float x) {
    float y; asm("ex2.approx.f32 %0, %1;" : "=f"(y) : "f"(x)); return y;
}
__device__ __forceinline__ float lg2_approx(float x) {
    float y; asm("lg2.approx.f32 %0, %1;" : "=f"(y) : "f"(x)); return y;
}

// mu-law (0..255) -> linear.  exp(u/128*ln256) == 2^(u/16)
__device__ __forceinline__ float u2l(float v) {
    float u = v - 128.0f;
    float m = fmaf(SCALE_1, ex2_approx(fabsf(u) * 0.0625f), -SCALE_1);
    return copysignf(m, u);   // m >= 0, sign of u
}
// l2u(-x) = clip(128 - copysign(16*log2(1 + SCALE*|x|), x), 0, 255)
__device__ __forceinline__ float l2u_neg(float x) {
    float u = lg2_approx(fmaf(SCALE, fabsf(x), 1.0f));
    return fminf(fmaxf(fmaf(copysignf(16.0f, x), u, 128.0f) - 2.0f * copysignf(16.0f, x) * u + copysignf(16.0f, x) * u, 0.0f), 255.0f);
}
// (simpler, equivalent form actually used below)
__device__ __forceinline__ float l2u_neg2(float x) {
    float u = lg2_approx(fmaf(SCALE, fabsf(x), 1.0f));
    float s = copysignf(16.0f, x);                 // +-16 with x's sign
    return fminf(fmaxf(fmaf(-s, u, 128.0f), 0.0f), 255.0f);
}

__device__ __forceinline__ float4 dec4(float4 v) {
    float4 d;
    d.x = u2l(v.x); d.y = u2l(v.y); d.z = u2l(v.z); d.w = u2l(v.w);
    return d;
}

// One block = one (row, 3-frame chunk). 64 threads: threads 0..59 each
// produce 8 consecutive output samples (2 float4 stores) with a 24-sample
// register window (6 LDS.128) and 16 broadcast coefficients.
__global__ __launch_bounds__(NTHREADS)
void diff_pred_kernel(const float4* __restrict__ sig,
                      const float*  __restrict__ lpc,
                      float4* __restrict__ out) {
    __shared__ __align__(16) float sx[LPC_N + CHUNK];   // halo + decoded chunk
    __shared__ __align__(16) float sl[FPB * LPC_N];     // 48 coefficients
    float4* sx4 = (float4*)sx;

    const int bx  = blockIdx.x;
    const int b   = bx / CHUNKS_PER_B;
    const int ck  = bx % CHUNKS_PER_B;
    const int tid = threadIdx.x;
    const int row4 = b * T4 + ck * CHUNK4;   // float4 index of chunk start

    // Decode pass 1: float4 groups 0..63
    sx4[4 + tid] = dec4(sig[row4 + tid]);
    // Decode pass 2: groups 64..119, and halo groups by threads 56..59
    {
        int i2 = tid + 64;
        if (i2 < CHUNK4) {
            sx4[4 + i2] = dec4(sig[row4 + i2]);
        } else if (i2 < CHUNK4 + 4) {
            int k = i2 - CHUNK4;             // 0..3
            sx4[k] = (ck == 0) ? make_float4(0.f, 0.f, 0.f, 0.f)
                               : dec4(sig[row4 - 4 + k]);
        }
    }
    if (tid < FPB * LPC_N)
        sl[tid] = lpc[b * (N_FRAMES * LPC_N) + ck * (FPB * LPC_N) + tid];
    __syncthreads();

    if (tid >= NWORK) return;

    // frame within chunk for this thread's 8 samples (160 % 8 == 0)
    const int f = tid / (FRAME_SIZE / 8);    // tid / 20 -> 0..2

    // 16 coefficients (4 broadcast LDS.128)
    float c[LPC_N];
#pragma unroll
    for (int i = 0; i < LPC_N; i += 4) {
        float4 cc = *(const float4*)&sl[f * LPC_N + i];
        c[i] = cc.x; c[i + 1] = cc.y; c[i + 2] = cc.z; c[i + 3] = cc.w;
    }

    // 24-sample window sx[8*tid .. 8*tid+23] (6 LDS.128)
    float x[24];
#pragma unroll
    for (int k = 0; k < 6; ++k) {
        float4 xx = sx4[2 * tid + k];
        x[4 * k] = xx.x; x[4 * k + 1] = xx.y; x[4 * k + 2] = xx.z; x[4 * k + 3] = xx.w;
    }

    // output j (0..7) = sum_i c[i] * x[16 + j - i]
    float a[8];
#pragma unroll
    for (int j = 0; j < 8; ++j) a[j] = 0.0f;
#pragma unroll
    for (int i = 0; i < LPC_N; ++i) {
#pragma unroll
        for (int j = 0; j < 8; ++j)
            a[j] = fmaf(c[i], x[16 + j - i], a[j]);
    }

    float4 r0, r1;
    r0.x = l2u_neg2(a[0]); r0.y = l2u_neg2(a[1]);
    r0.z = l2u_neg2(a[2]); r0.w = l2u_neg2(a[3]);
    r1.x = l2u_neg2(a[4]); r1.y = l2u_neg2(a[5]);
    r1.z = l2u_neg2(a[6]); r1.w = l2u_neg2(a[7]);

    out[row4 + 2 * tid]     = r0;
    out[row4 + 2 * tid + 1] = r1;
}

extern "C" void kernel_launch(void* const* d_in, const int* in_sizes, int n_in,
                              void* d_out, int out_size) {
    const float4* sig = (const float4*)d_in[0];  // (B, 2400, 1) f32
    const float*  lpc = (const float*)d_in[1];   // (B, 15, 16) f32
    float4* out = (float4*)d_out;                // (B, 2400, 1) f32

    dim3 grid(B_SZ * CHUNKS_PER_B);              // 5120 blocks
    dim3 block(NTHREADS);
    diff_pred_kernel<<<grid, block>>>(sig, lpc, out);
}